// round 16
// baseline (speedup 1.0000x reference)
#include <cuda_runtime.h>
#include <math.h>

#define N_IMG 16
#define IMG_Q 4                 // images per pipeline stage
#define N_STAGES (N_IMG / IMG_Q)
#define H 1024
#define W 1024
#define HW (H * W)
#define TOT (N_IMG * HW)
#define RAD 8
#define KLEN 17
#define WW64 (W / 64)
#define WW32 (W / 32)

typedef unsigned long long ull;

// gaussian(sigma=2,r=8) weights as compile-time literals
__device__ __forceinline__ float gw(int k) {
    switch (k) {
        case 0: case 16: return 6.6916292e-05f;
        case 1: case 15: return 4.3634888e-04f;
        case 2: case 14: return 2.2159620e-03f;
        case 3: case 13: return 8.7643044e-03f;
        case 4: case 12: return 2.6995958e-02f;
        case 5: case 11: return 6.4759926e-02f;
        case 6: case 10: return 1.2098749e-01f;
        case 7: case 9:  return 1.7603576e-01f;
        default:         return 1.9947465e-01f;
    }
}
__device__ __forceinline__ ull gw2(int k) {
    unsigned b = __float_as_uint(gw(k));
    return (ull)b | ((ull)b << 32);
}

// ---------------- scratch ----------------
__device__ float g_t1[TOT];
__device__ ull g_strong64[TOT / 64];
__device__ ull g_weak64[TOT / 64];
__device__ double g_acc = 0.0;     // finalizer re-zeroes after each launch
__device__ unsigned int g_ticket = 0;

__device__ __forceinline__ int reflect_idx(int i, int n) {
    if (i < 0) return -i;
    if (i >= n) return 2 * n - 2 - i;
    return i;
}

// ---------------- row blur: grid (H/4, IMG_Q), block 256 ----------------
#define RB_ROWS 4
__global__ void k_rowblur(const float* __restrict__ x, int n0) {
    __shared__ __align__(16) float sm[RB_ROWS][W + 2 * RAD];
    int tid = threadIdx.x;
    int r0 = blockIdx.x * RB_ROWS;
    int n = blockIdx.y + n0;
#pragma unroll
    for (int rr = 0; rr < RB_ROWS; rr++) {
        const float* src = x + ((size_t)n * HW + (size_t)(r0 + rr) * W);
        reinterpret_cast<float4*>(sm[rr] + RAD)[tid] = reinterpret_cast<const float4*>(src)[tid];
        if (tid < RAD) {
            sm[rr][tid] = src[RAD - tid];
            sm[rr][W + RAD + tid] = src[W - 2 - tid];
        }
    }
    __syncthreads();
    int j = tid * 4;
#pragma unroll
    for (int rr = 0; rr < RB_ROWS; rr++) {
        float r[20];
#pragma unroll
        for (int q = 0; q < 5; q++) {
            float4 v = *reinterpret_cast<const float4*>(sm[rr] + j + q * 4);
            r[q * 4 + 0] = v.x; r[q * 4 + 1] = v.y; r[q * 4 + 2] = v.z; r[q * 4 + 3] = v.w;
        }
        float a0 = 0.f, a1 = 0.f, a2 = 0.f, a3 = 0.f;
#pragma unroll
        for (int k = 0; k < KLEN; k++) {
            float wk = gw(k);
            a0 += wk * r[k]; a1 += wk * r[k + 1]; a2 += wk * r[k + 2]; a3 += wk * r[k + 3];
        }
        float* dst = g_t1 + ((size_t)n * HW + (size_t)(r0 + rr) * W);
        reinterpret_cast<float4*>(dst)[tid] = make_float4(a0, a1, a2, a3);
    }
}

// ---------------- fused colblur + sobel(mag^2) + NMS + thresholds ----------------
#define TILE_H 128
#define T1R 148
#define T1C 40
#define SSR 132
#define MGSTRIDE 36

__device__ __forceinline__ signed char dir_off(float u, float v) {
    if (v < 0.f || (v == 0.f && u < 0.f)) { u = -u; v = -v; }
    const float c1 = 0.41421356237309503f;
    const float c2 = 2.414213562373095f;
    if (u > 0.f) {
        if (v < c1 * u)      return 1;
        else if (v < c2 * u) return -(MGSTRIDE - 1);
        else                 return -MGSTRIDE;
    } else if (u < 0.f) {
        float t = -u;
        if (v <= c1 * t)     return 1;
        else if (v > c2 * t) return -MGSTRIDE;
        else                 return -(MGSTRIDE + 1);
    }
    return -MGSTRIDE;
}

__global__ void __launch_bounds__(256) k_colsobel(int n0) {
    __shared__ __align__(16) float sA[T1R * T1C];   // raw; later mag^2 (stride 36)
    __shared__ __align__(16) float sS[SSR * T1C];   // smoothed
    __shared__ signed char sB[TILE_H * 32];
    int tx = threadIdx.x, ty = threadIdx.y;
    int tid = ty * 32 + tx;
    int c0 = blockIdx.x * 32;
    int r0 = blockIdx.y * TILE_H;
    int n = blockIdx.z + n0;
    const float* src = g_t1 + (size_t)n * HW;

    bool interior = (r0 != 0) && (r0 != H - TILE_H) && (c0 != 0) && (c0 != W - 32);
    if (interior) {
        const float* base = src + (size_t)(r0 - 10) * W + (c0 - 4);
        for (int i = tid; i < T1R * 10; i += 256) {
            int rr = i / 10, q = i - rr * 10;
            *reinterpret_cast<float4*>(sA + rr * T1C + q * 4) =
                *reinterpret_cast<const float4*>(base + (size_t)rr * W + q * 4);
        }
    } else {
        for (int i = tid; i < T1R * T1C; i += 256) {
            int rr = i / T1C, cc = i - rr * T1C;
            int gi = reflect_idx(r0 - 10 + rr, H);
            int gj = reflect_idx(c0 - 4 + cc, W);
            sA[i] = src[(size_t)gi * W + gj];
        }
    }
    __syncthreads();

    // phase A: vertical blur via register streaming + packed f32x2 FMA
    {
        int q = tid % 10;
        int b = tid / 10;
        if (b < 22) {
            const float* p = sA + (6 * b) * T1C + q * 4;
            ull acc[6][2];
#pragma unroll
            for (int o = 0; o < 6; o++) { acc[o][0] = 0ULL; acc[o][1] = 0ULL; }
#pragma unroll
            for (int i = 0; i < 22; i++) {
                float4 v = *reinterpret_cast<const float4*>(p + i * T1C);
                ull p01, p23;
                asm("mov.b64 %0, {%1, %2};" : "=l"(p01) : "f"(v.x), "f"(v.y));
                asm("mov.b64 %0, {%1, %2};" : "=l"(p23) : "f"(v.z), "f"(v.w));
#pragma unroll
                for (int o = 0; o < 6; o++) {
                    int k = i - o;
                    if (k >= 0 && k < KLEN) {
                        ull w2 = gw2(k);
                        asm("fma.rn.f32x2 %0, %1, %2, %0;" : "+l"(acc[o][0]) : "l"(p01), "l"(w2));
                        asm("fma.rn.f32x2 %0, %1, %2, %0;" : "+l"(acc[o][1]) : "l"(p23), "l"(w2));
                    }
                }
            }
            float* d = sS + (6 * b) * T1C + q * 4;
#pragma unroll
            for (int o = 0; o < 6; o++)
                *reinterpret_cast<ulonglong2*>(d + o * T1C) =
                    make_ulonglong2(acc[o][0], acc[o][1]);
        }
    }
    __syncthreads();

    // phase B: mag^2 + direction via 3x3 rolling window (3 loads/px)
    {
        int c = tid % 34;
        int b = tid / 34;
        if (b < 7) {
            int rstart = 19 * b;
            const float* p = sS + rstart * T1C + c + 2;
            float a0 = p[0], a1 = p[1], a2 = p[2];
            float b0 = p[T1C], b1 = p[T1C + 1], b2 = p[T1C + 2];
#pragma unroll
            for (int r = 0; r < 19; r++) {
                int rm = rstart + r;
                if (rm < 130) {
                    const float* pr = p + (r + 2) * T1C;
                    float e0 = pr[0], e1 = pr[1], e2 = pr[2];
                    float gx = (a2 - a0) + 2.f * (b2 - b0) + (e2 - e0);
                    float gy = (e0 + 2.f * e1 + e2) - (a0 + 2.f * a1 + a2);
                    sA[rm * MGSTRIDE + c] = gx * gx + gy * gy;
                    if (rm >= 1 && rm <= TILE_H && c >= 1 && c <= 32)
                        sB[(rm - 1) * 32 + (c - 1)] = dir_off(gx, gy);
                    a0 = b0; a1 = b1; a2 = b2;
                    b0 = e0; b1 = e1; b2 = e2;
                }
            }
        }
    }
    __syncthreads();

    // border zeroing only on border tiles (block-uniform predicate)
    if (!interior) {
        if (r0 == 0 && tid < 34) sA[tid] = 0.f;
        if (r0 == H - TILE_H && tid < 34) sA[129 * MGSTRIDE + tid] = 0.f;
        if (c0 == 0) { for (int i = tid; i < 130; i += 256) sA[i * MGSTRIDE] = 0.f; }
        if (c0 == W - 32) { for (int i = tid; i < 130; i += 256) sA[i * MGSTRIDE + 33] = 0.f; }
        __syncthreads();
    }

    const float TH2 = 0.04f;
    const float TL2 = 0.01f;
    unsigned int* S32 = reinterpret_cast<unsigned int*>(g_strong64);
    unsigned int* W32 = reinterpret_cast<unsigned int*>(g_weak64);
    size_t base = (size_t)n * (HW / 32) + (size_t)blockIdx.x;
#pragma unroll
    for (int s = 0; s < 16; s++) {
        int lr = ty * 16 + s;
        int ci = (lr + 1) * MGSTRIDE + (tx + 1);
        float mc = sA[ci];
        int off = sB[lr * 32 + tx];
        bool keep = (mc >= sA[ci + off]) && (mc >= sA[ci - off]);
        bool strong = keep && (mc > TH2);
        bool weak = keep && (mc > TL2);
        unsigned ws = __ballot_sync(0xffffffffu, strong);
        unsigned ww = __ballot_sync(0xffffffffu, weak);
        if (tx == 0) {
            size_t widx = base + (size_t)(r0 + lr) * WW32;
            S32[widx] = ws;
            W32[widx] = ww;
        }
    }
}

// ---------------- hysteresis: full-height strips, single pass ----------------
__device__ __forceinline__ ull rowfill(ull s, ull w) {
    ull up = ((w + s) ^ w) & w;
    ull rs = __brevll(s), rwv = __brevll(w);
    ull dn = __brevll(((rwv + rs) ^ rwv) & rwv);
    return s | up | dn;
}
#define HHX(v) ((v) | ((v) << 1) | ((v) >> 1))

__global__ void k_hyst(int n0) {
    const int bx = blockIdx.x;
    const int n = blockIdx.y + n0;
    const int t = threadIdx.x;

    __shared__ ull sTop[2][256], sBot[2][256];
    __shared__ unsigned char lbs[1026], rbs[1026];

    ull* S = g_strong64 + (size_t)n * (HW / 64);
    const ull* Wk = g_weak64 + (size_t)n * (HW / 64);

    int gr0 = t * 4;
    ull s[4], w[4];
#pragma unroll
    for (int j = 0; j < 4; j++) {
        size_t off = (size_t)(gr0 + j) * WW64 + bx;
        s[j] = S[off];
        w[j] = Wk[off];
        lbs[gr0 + j + 1] = (bx > 0)        ? (unsigned char)(S[off - 1] >> 63) : 0;
        rbs[gr0 + j + 1] = (bx < WW64 - 1) ? (unsigned char)(S[off + 1] & 1ULL) : 0;
    }
    if (t == 0) { lbs[0] = rbs[0] = lbs[1025] = rbs[1025] = 0; }
    sTop[0][t] = s[0]; sBot[0][t] = s[3];
    __syncthreads();

    ull LR[4];
#pragma unroll
    for (int j = 0; j < 4; j++) {
        int i = gr0 + j;
        unsigned l = (unsigned)(lbs[i] | lbs[i + 1] | lbs[i + 2]);
        unsigned r = (unsigned)(rbs[i] | rbs[i + 1] | rbs[i + 2]);
        LR[j] = (ull)(l & 1u) | ((ull)(r & 1u) << 63);
    }

    int any = 0;
    int pb = 0;
    while (true) {
        ull above = (t > 0)   ? sBot[pb][t - 1] : 0ULL;
        ull below = (t < 255) ? sTop[pb][t + 1] : 0ULL;
        ull o0 = s[0], o1 = s[1], o2 = s[2], o3 = s[3];
        s[0] |= (HHX(above) | HHX(s[0]) | HHX(s[1]) | LR[0]) & w[0]; s[0] = rowfill(s[0], w[0]);
        s[1] |= (HHX(s[0])  | HHX(s[1]) | HHX(s[2]) | LR[1]) & w[1]; s[1] = rowfill(s[1], w[1]);
        s[2] |= (HHX(s[1])  | HHX(s[2]) | HHX(s[3]) | LR[2]) & w[2]; s[2] = rowfill(s[2], w[2]);
        s[3] |= (HHX(s[2])  | HHX(s[3]) | HHX(below)| LR[3]) & w[3]; s[3] = rowfill(s[3], w[3]);
        s[2] |= (HHX(s[1]) | HHX(s[2]) | HHX(s[3]) | LR[2]) & w[2]; s[2] = rowfill(s[2], w[2]);
        s[1] |= (HHX(s[0]) | HHX(s[1]) | HHX(s[2]) | LR[1]) & w[1]; s[1] = rowfill(s[1], w[1]);
        s[0] |= (HHX(above)| HHX(s[0]) | HHX(s[1]) | LR[0]) & w[0]; s[0] = rowfill(s[0], w[0]);
        int ch = (s[0] != o0) | (s[1] != o1) | (s[2] != o2) | (s[3] != o3);
        any |= ch;
        sTop[pb ^ 1][t] = s[0]; sBot[pb ^ 1][t] = s[3];
        pb ^= 1;
        if (!__syncthreads_or(ch)) break;
    }

    if (any) {
#pragma unroll
        for (int j = 0; j < 4; j++) S[(size_t)(gr0 + j) * WW64 + bx] = s[j];
    }
}

// ---------------- loss: warp-contiguous, fully coalesced; 512 blocks/stage --------
#define LOSS_BLOCKS 512
#define LOSS_TOTAL_BLOCKS (LOSS_BLOCKS * N_STAGES)
__global__ void k_loss(const float* __restrict__ y, const float* __restrict__ mask,
                       float* __restrict__ out, int n0) {
    const unsigned int* S32 = reinterpret_cast<const unsigned int*>(g_strong64);
    int gid = blockIdx.x * 256 + threadIdx.x;
    int warpg = gid >> 5;                      // 0..4095 within this stage
    int lane = gid & 31;
    size_t pbase = (size_t)n0 * HW + (size_t)warpg * 1024;

    unsigned int wbits = S32[(size_t)n0 * (HW / 32) + warpg * 32 + lane];
    const float4* y4 = reinterpret_cast<const float4*>(y + pbase);
    const float4* m4 = reinterpret_cast<const float4*>(mask + ((size_t)warpg * 1024 & (HW - 1)));

    float acc = 0.f;
#pragma unroll
    for (int j = 0; j < 8; j++) {
        float4 yy = y4[j * 32 + lane];
        float4 mm = m4[j * 32 + lane];
        unsigned srcw = __shfl_sync(0xffffffffu, wbits, j * 4 + (lane >> 3));
        unsigned b = (srcw >> ((lane & 7) * 4)) & 0xFu;
        float p0 = yy.x * mm.x, p1 = yy.y * mm.y;
        float p2 = yy.z * mm.z, p3 = yy.w * mm.w;
        acc += (b & 1u)        ? fabsf(mm.x - p0) : p0;
        acc += ((b >> 1) & 1u) ? fabsf(mm.y - p1) : p1;
        acc += ((b >> 2) & 1u) ? fabsf(mm.z - p2) : p2;
        acc += ((b >> 3) & 1u) ? fabsf(mm.w - p3) : p3;
    }
#pragma unroll
    for (int off = 16; off; off >>= 1) acc += __shfl_down_sync(0xffffffffu, acc, off);
    __shared__ float sred[8];
    int wid = threadIdx.x >> 5;
    int l = threadIdx.x & 31;
    if (l == 0) sred[wid] = acc;
    __syncthreads();
    if (wid == 0) {
        acc = (l < 8) ? sred[l] : 0.f;
#pragma unroll
        for (int off = 4; off; off >>= 1) acc += __shfl_down_sync(0xffffffffu, acc, off);
        if (l == 0) atomicAdd(&g_acc, (double)acc);
    }
    if (threadIdx.x == 0) {
        __threadfence();
        unsigned int ticket = atomicAdd(&g_ticket, 1u);
        if (ticket == LOSS_TOTAL_BLOCKS - 1) {
            double v = atomicAdd(&g_acc, 0.0);
            out[0] = (float)(v * (1.0 / (double)HW));
            g_acc = 0.0;          // leave zeroed for next (graph-replayed) launch
            g_ticket = 0;
        }
    }
}

// ---------------- launch: 4-stream pipeline over image quarters ----------------
extern "C" void kernel_launch(void* const* d_in, const int* in_sizes, int n_in,
                              void* d_out, int out_size) {
    const float* x = nullptr;
    const float* y = nullptr;
    const float* mask = nullptr;
    for (int i = 0; i < n_in; i++) {
        if (in_sizes[i] == HW && mask == nullptr) mask = (const float*)d_in[i];
        else if (x == nullptr) x = (const float*)d_in[i];
        else if (y == nullptr) y = (const float*)d_in[i];
    }

    static cudaStream_t st[N_STAGES - 1] = {};
    static cudaEvent_t evFork = nullptr;
    static cudaEvent_t evJoin[N_STAGES - 1] = {};
    if (evFork == nullptr) {
        cudaEventCreateWithFlags(&evFork, cudaEventDisableTiming);
        for (int i = 0; i < N_STAGES - 1; i++) {
            cudaStreamCreateWithFlags(&st[i], cudaStreamNonBlocking);
            cudaEventCreateWithFlags(&evJoin[i], cudaEventDisableTiming);
        }
    }

    cudaEventRecord(evFork, 0);
    for (int i = 0; i < N_STAGES - 1; i++) cudaStreamWaitEvent(st[i], evFork, 0);

    for (int q = 0; q < N_STAGES; q++) {
        cudaStream_t s = (q == 0) ? (cudaStream_t)0 : st[q - 1];
        int n0 = q * IMG_Q;
        k_rowblur<<<dim3(H / RB_ROWS, IMG_Q), 256, 0, s>>>(x, n0);
        k_colsobel<<<dim3(W / 32, H / TILE_H, IMG_Q), dim3(32, 8), 0, s>>>(n0);
        k_hyst<<<dim3(WW64, IMG_Q), 256, 0, s>>>(n0);
        k_loss<<<LOSS_BLOCKS, 256, 0, s>>>(y, mask, (float*)d_out, n0);
    }

    for (int i = 0; i < N_STAGES - 1; i++) {
        cudaEventRecord(evJoin[i], st[i]);
        cudaStreamWaitEvent(0, evJoin[i], 0);
    }
}

// round 17
// speedup vs baseline: 1.0734x; 1.0734x over previous
#include <cuda_runtime.h>
#include <math.h>

#define N_IMG 16
#define IMG_HALF 8
#define H 1024
#define W 1024
#define HW (H * W)
#define TOT (N_IMG * HW)
#define RAD 8
#define KLEN 17
#define WW64 (W / 64)
#define WW32 (W / 32)

typedef unsigned long long ull;

// gaussian(sigma=2,r=8) weights as compile-time literals
__device__ __forceinline__ float gw(int k) {
    switch (k) {
        case 0: case 16: return 6.6916292e-05f;
        case 1: case 15: return 4.3634888e-04f;
        case 2: case 14: return 2.2159620e-03f;
        case 3: case 13: return 8.7643044e-03f;
        case 4: case 12: return 2.6995958e-02f;
        case 5: case 11: return 6.4759926e-02f;
        case 6: case 10: return 1.2098749e-01f;
        case 7: case 9:  return 1.7603576e-01f;
        default:         return 1.9947465e-01f;
    }
}
__device__ __forceinline__ ull gw2(int k) {
    unsigned b = __float_as_uint(gw(k));
    return (ull)b | ((ull)b << 32);
}

// ---------------- scratch ----------------
__device__ float g_t1[TOT];
__device__ ull g_strong64[TOT / 64];
__device__ ull g_weak64[TOT / 64];
__device__ double g_acc = 0.0;     // finalizer re-zeroes after each launch
__device__ unsigned int g_ticket = 0;

__device__ __forceinline__ int reflect_idx(int i, int n) {
    if (i < 0) return -i;
    if (i >= n) return 2 * n - 2 - i;
    return i;
}

// ---------------- row blur: grid (H/4, 8), block 256 ----------------
#define RB_ROWS 4
__global__ void k_rowblur(const float* __restrict__ x, int n0) {
    __shared__ __align__(16) float sm[RB_ROWS][W + 2 * RAD];
    int tid = threadIdx.x;
    int r0 = blockIdx.x * RB_ROWS;
    int n = blockIdx.y + n0;
#pragma unroll
    for (int rr = 0; rr < RB_ROWS; rr++) {
        const float* src = x + ((size_t)n * HW + (size_t)(r0 + rr) * W);
        reinterpret_cast<float4*>(sm[rr] + RAD)[tid] = reinterpret_cast<const float4*>(src)[tid];
        if (tid < RAD) {
            sm[rr][tid] = src[RAD - tid];
            sm[rr][W + RAD + tid] = src[W - 2 - tid];
        }
    }
    __syncthreads();
    int j = tid * 4;
#pragma unroll
    for (int rr = 0; rr < RB_ROWS; rr++) {
        float r[20];
#pragma unroll
        for (int q = 0; q < 5; q++) {
            float4 v = *reinterpret_cast<const float4*>(sm[rr] + j + q * 4);
            r[q * 4 + 0] = v.x; r[q * 4 + 1] = v.y; r[q * 4 + 2] = v.z; r[q * 4 + 3] = v.w;
        }
        float a0 = 0.f, a1 = 0.f, a2 = 0.f, a3 = 0.f;
#pragma unroll
        for (int k = 0; k < KLEN; k++) {
            float wk = gw(k);
            a0 += wk * r[k]; a1 += wk * r[k + 1]; a2 += wk * r[k + 2]; a3 += wk * r[k + 3];
        }
        float* dst = g_t1 + ((size_t)n * HW + (size_t)(r0 + rr) * W);
        reinterpret_cast<float4*>(dst)[tid] = make_float4(a0, a1, a2, a3);
    }
}

// ---------------- fused colblur + sobel(mag^2) + NMS + thresholds ----------------
// direction code (2 bits) embedded in low mantissa bits of mag^2 -> sB eliminated
#define TILE_H 128
#define T1R 148
#define T1C 40
#define SSR 132
#define MGSTRIDE 36

__device__ __forceinline__ unsigned dir_code(float u, float v) {
    if (v < 0.f || (v == 0.f && u < 0.f)) { u = -u; v = -v; }
    const float c1 = 0.41421356237309503f;
    const float c2 = 2.414213562373095f;
    if (u > 0.f) {
        if (v < c1 * u)      return 0u;   // off = +1
        else if (v < c2 * u) return 1u;   // off = -(MGSTRIDE-1)
        else                 return 2u;   // off = -MGSTRIDE
    } else if (u < 0.f) {
        float t = -u;
        if (v <= c1 * t)     return 0u;
        else if (v > c2 * t) return 2u;
        else                 return 3u;   // off = -(MGSTRIDE+1)
    }
    return 2u;
}

__global__ void __launch_bounds__(256) k_colsobel(int n0) {
    __shared__ __align__(16) float sA[T1R * T1C];   // raw; later mag^2+dir (stride 36)
    __shared__ __align__(16) float sS[SSR * T1C];   // smoothed
    int tx = threadIdx.x, ty = threadIdx.y;
    int tid = ty * 32 + tx;
    int c0 = blockIdx.x * 32;
    int r0 = blockIdx.y * TILE_H;
    int n = blockIdx.z + n0;
    const float* src = g_t1 + (size_t)n * HW;

    bool interior = (r0 != 0) && (r0 != H - TILE_H) && (c0 != 0) && (c0 != W - 32);
    if (interior) {
        const float* base = src + (size_t)(r0 - 10) * W + (c0 - 4);
        for (int i = tid; i < T1R * 10; i += 256) {
            int rr = i / 10, q = i - rr * 10;
            *reinterpret_cast<float4*>(sA + rr * T1C + q * 4) =
                *reinterpret_cast<const float4*>(base + (size_t)rr * W + q * 4);
        }
    } else {
        for (int i = tid; i < T1R * T1C; i += 256) {
            int rr = i / T1C, cc = i - rr * T1C;
            int gi = reflect_idx(r0 - 10 + rr, H);
            int gj = reflect_idx(c0 - 4 + cc, W);
            sA[i] = src[(size_t)gi * W + gj];
        }
    }
    __syncthreads();

    // phase A: vertical blur via register streaming + packed f32x2 FMA
    {
        int q = tid % 10;
        int b = tid / 10;
        if (b < 22) {
            const float* p = sA + (6 * b) * T1C + q * 4;
            ull acc[6][2];
#pragma unroll
            for (int o = 0; o < 6; o++) { acc[o][0] = 0ULL; acc[o][1] = 0ULL; }
#pragma unroll
            for (int i = 0; i < 22; i++) {
                float4 v = *reinterpret_cast<const float4*>(p + i * T1C);
                ull p01, p23;
                asm("mov.b64 %0, {%1, %2};" : "=l"(p01) : "f"(v.x), "f"(v.y));
                asm("mov.b64 %0, {%1, %2};" : "=l"(p23) : "f"(v.z), "f"(v.w));
#pragma unroll
                for (int o = 0; o < 6; o++) {
                    int k = i - o;
                    if (k >= 0 && k < KLEN) {
                        ull w2 = gw2(k);
                        asm("fma.rn.f32x2 %0, %1, %2, %0;" : "+l"(acc[o][0]) : "l"(p01), "l"(w2));
                        asm("fma.rn.f32x2 %0, %1, %2, %0;" : "+l"(acc[o][1]) : "l"(p23), "l"(w2));
                    }
                }
            }
            float* d = sS + (6 * b) * T1C + q * 4;
#pragma unroll
            for (int o = 0; o < 6; o++)
                *reinterpret_cast<ulonglong2*>(d + o * T1C) =
                    make_ulonglong2(acc[o][0], acc[o][1]);
        }
    }
    __syncthreads();

    // phase B: mag^2 (low 2 bits = dir code) via 3x3 rolling window
    {
        int c = tid % 34;
        int b = tid / 34;
        if (b < 7) {
            int rstart = 19 * b;
            const float* p = sS + rstart * T1C + c + 2;
            float a0 = p[0], a1 = p[1], a2 = p[2];
            float b0 = p[T1C], b1 = p[T1C + 1], b2 = p[T1C + 2];
#pragma unroll
            for (int r = 0; r < 19; r++) {
                int rm = rstart + r;
                if (rm < 130) {
                    const float* pr = p + (r + 2) * T1C;
                    float e0 = pr[0], e1 = pr[1], e2 = pr[2];
                    float gx = (a2 - a0) + 2.f * (b2 - b0) + (e2 - e0);
                    float gy = (e0 + 2.f * e1 + e2) - (a0 + 2.f * a1 + a2);
                    float m2 = gx * gx + gy * gy;
                    unsigned u = (__float_as_uint(m2) & ~3u) | dir_code(gx, gy);
                    sA[rm * MGSTRIDE + c] = __uint_as_float(u);
                    a0 = b0; a1 = b1; a2 = b2;
                    b0 = e0; b1 = e1; b2 = e2;
                }
            }
        }
    }
    __syncthreads();

    // border zeroing only on border tiles (block-uniform predicate)
    if (!interior) {
        if (r0 == 0 && tid < 34) sA[tid] = 0.f;
        if (r0 == H - TILE_H && tid < 34) sA[129 * MGSTRIDE + tid] = 0.f;
        if (c0 == 0) { for (int i = tid; i < 130; i += 256) sA[i * MGSTRIDE] = 0.f; }
        if (c0 == W - 32) { for (int i = tid; i < 130; i += 256) sA[i * MGSTRIDE + 33] = 0.f; }
        __syncthreads();
    }

    const float TH2 = 0.04f;
    const float TL2 = 0.01f;
    unsigned int* S32 = reinterpret_cast<unsigned int*>(g_strong64);
    unsigned int* W32 = reinterpret_cast<unsigned int*>(g_weak64);
    size_t base = (size_t)n * (HW / 32) + (size_t)blockIdx.x;
#pragma unroll
    for (int s = 0; s < 16; s++) {
        int lr = ty * 16 + s;
        int ci = (lr + 1) * MGSTRIDE + (tx + 1);
        float mc = sA[ci];
        unsigned code = __float_as_uint(mc) & 3u;
        int off = (code == 0u) ? 1 : -(34 + (int)code);
        bool keep = (mc >= sA[ci + off]) && (mc >= sA[ci - off]);
        bool strong = keep && (mc > TH2);
        bool weak = keep && (mc > TL2);
        unsigned ws = __ballot_sync(0xffffffffu, strong);
        unsigned ww = __ballot_sync(0xffffffffu, weak);
        if (tx == 0) {
            size_t widx = base + (size_t)(r0 + lr) * WW32;
            S32[widx] = ws;
            W32[widx] = ww;
        }
    }
}

// ---------------- hysteresis: full-height strips, single pass ----------------
__device__ __forceinline__ ull rowfill(ull s, ull w) {
    ull up = ((w + s) ^ w) & w;
    ull rs = __brevll(s), rwv = __brevll(w);
    ull dn = __brevll(((rwv + rs) ^ rwv) & rwv);
    return s | up | dn;
}
#define HHX(v) ((v) | ((v) << 1) | ((v) >> 1))

__global__ void k_hyst(int n0) {
    const int bx = blockIdx.x;
    const int n = blockIdx.y + n0;
    const int t = threadIdx.x;

    __shared__ ull sTop[2][256], sBot[2][256];
    __shared__ unsigned char lbs[1026], rbs[1026];

    ull* S = g_strong64 + (size_t)n * (HW / 64);
    const ull* Wk = g_weak64 + (size_t)n * (HW / 64);

    int gr0 = t * 4;
    ull s[4], w[4];
#pragma unroll
    for (int j = 0; j < 4; j++) {
        size_t off = (size_t)(gr0 + j) * WW64 + bx;
        s[j] = S[off];
        w[j] = Wk[off];
        lbs[gr0 + j + 1] = (bx > 0)        ? (unsigned char)(S[off - 1] >> 63) : 0;
        rbs[gr0 + j + 1] = (bx < WW64 - 1) ? (unsigned char)(S[off + 1] & 1ULL) : 0;
    }
    if (t == 0) { lbs[0] = rbs[0] = lbs[1025] = rbs[1025] = 0; }
    sTop[0][t] = s[0]; sBot[0][t] = s[3];
    __syncthreads();

    ull LR[4];
#pragma unroll
    for (int j = 0; j < 4; j++) {
        int i = gr0 + j;
        unsigned l = (unsigned)(lbs[i] | lbs[i + 1] | lbs[i + 2]);
        unsigned r = (unsigned)(rbs[i] | rbs[i + 1] | rbs[i + 2]);
        LR[j] = (ull)(l & 1u) | ((ull)(r & 1u) << 63);
    }

    int any = 0;
    int pb = 0;
    while (true) {
        ull above = (t > 0)   ? sBot[pb][t - 1] : 0ULL;
        ull below = (t < 255) ? sTop[pb][t + 1] : 0ULL;
        ull o0 = s[0], o1 = s[1], o2 = s[2], o3 = s[3];
        s[0] |= (HHX(above) | HHX(s[0]) | HHX(s[1]) | LR[0]) & w[0]; s[0] = rowfill(s[0], w[0]);
        s[1] |= (HHX(s[0])  | HHX(s[1]) | HHX(s[2]) | LR[1]) & w[1]; s[1] = rowfill(s[1], w[1]);
        s[2] |= (HHX(s[1])  | HHX(s[2]) | HHX(s[3]) | LR[2]) & w[2]; s[2] = rowfill(s[2], w[2]);
        s[3] |= (HHX(s[2])  | HHX(s[3]) | HHX(below)| LR[3]) & w[3]; s[3] = rowfill(s[3], w[3]);
        s[2] |= (HHX(s[1]) | HHX(s[2]) | HHX(s[3]) | LR[2]) & w[2]; s[2] = rowfill(s[2], w[2]);
        s[1] |= (HHX(s[0]) | HHX(s[1]) | HHX(s[2]) | LR[1]) & w[1]; s[1] = rowfill(s[1], w[1]);
        s[0] |= (HHX(above)| HHX(s[0]) | HHX(s[1]) | LR[0]) & w[0]; s[0] = rowfill(s[0], w[0]);
        int ch = (s[0] != o0) | (s[1] != o1) | (s[2] != o2) | (s[3] != o3);
        any |= ch;
        sTop[pb ^ 1][t] = s[0]; sBot[pb ^ 1][t] = s[3];
        pb ^= 1;
        if (!__syncthreads_or(ch)) break;
    }

    if (any) {
#pragma unroll
        for (int j = 0; j < 4; j++) S[(size_t)(gr0 + j) * WW64 + bx] = s[j];
    }
}

// ---------------- loss: warp-contiguous, fully coalesced; 1024 blocks per half ----
#define LOSS_BLOCKS 1024
#define LOSS_TOTAL_BLOCKS 2048
__global__ void k_loss(const float* __restrict__ y, const float* __restrict__ mask,
                       float* __restrict__ out, int n0) {
    const unsigned int* S32 = reinterpret_cast<const unsigned int*>(g_strong64);
    int gid = blockIdx.x * 256 + threadIdx.x;
    int warpg = gid >> 5;
    int lane = gid & 31;
    size_t pbase = (size_t)n0 * HW + (size_t)warpg * 1024;

    unsigned int wbits = S32[(size_t)n0 * (HW / 32) + warpg * 32 + lane];
    const float4* y4 = reinterpret_cast<const float4*>(y + pbase);
    const float4* m4 = reinterpret_cast<const float4*>(mask + ((size_t)warpg * 1024 & (HW - 1)));

    float acc = 0.f;
#pragma unroll
    for (int j = 0; j < 8; j++) {
        float4 yy = y4[j * 32 + lane];
        float4 mm = m4[j * 32 + lane];
        unsigned srcw = __shfl_sync(0xffffffffu, wbits, j * 4 + (lane >> 3));
        unsigned b = (srcw >> ((lane & 7) * 4)) & 0xFu;
        float p0 = yy.x * mm.x, p1 = yy.y * mm.y;
        float p2 = yy.z * mm.z, p3 = yy.w * mm.w;
        acc += (b & 1u)        ? fabsf(mm.x - p0) : p0;
        acc += ((b >> 1) & 1u) ? fabsf(mm.y - p1) : p1;
        acc += ((b >> 2) & 1u) ? fabsf(mm.z - p2) : p2;
        acc += ((b >> 3) & 1u) ? fabsf(mm.w - p3) : p3;
    }
#pragma unroll
    for (int off = 16; off; off >>= 1) acc += __shfl_down_sync(0xffffffffu, acc, off);
    __shared__ float sred[8];
    int wid = threadIdx.x >> 5;
    int l = threadIdx.x & 31;
    if (l == 0) sred[wid] = acc;
    __syncthreads();
    if (wid == 0) {
        acc = (l < 8) ? sred[l] : 0.f;
#pragma unroll
        for (int off = 4; off; off >>= 1) acc += __shfl_down_sync(0xffffffffu, acc, off);
        if (l == 0) atomicAdd(&g_acc, (double)acc);
    }
    if (threadIdx.x == 0) {
        __threadfence();
        unsigned int ticket = atomicAdd(&g_ticket, 1u);
        if (ticket == LOSS_TOTAL_BLOCKS - 1) {
            double v = atomicAdd(&g_acc, 0.0);
            out[0] = (float)(v * (1.0 / (double)HW));
            g_acc = 0.0;
            g_ticket = 0;
        }
    }
}

// ---------------- launch: two-stream pipeline over image halves ----------------
extern "C" void kernel_launch(void* const* d_in, const int* in_sizes, int n_in,
                              void* d_out, int out_size) {
    const float* x = nullptr;
    const float* y = nullptr;
    const float* mask = nullptr;
    for (int i = 0; i < n_in; i++) {
        if (in_sizes[i] == HW && mask == nullptr) mask = (const float*)d_in[i];
        else if (x == nullptr) x = (const float*)d_in[i];
        else if (y == nullptr) y = (const float*)d_in[i];
    }

    static cudaStream_t s1 = nullptr;
    static cudaEvent_t evFork = nullptr, evJoin = nullptr;
    if (s1 == nullptr) {
        cudaStreamCreateWithFlags(&s1, cudaStreamNonBlocking);
        cudaEventCreateWithFlags(&evFork, cudaEventDisableTiming);
        cudaEventCreateWithFlags(&evJoin, cudaEventDisableTiming);
    }

    cudaEventRecord(evFork, 0);
    cudaStreamWaitEvent(s1, evFork, 0);

    // half 0 on default stream
    k_rowblur<<<dim3(H / RB_ROWS, IMG_HALF), 256>>>(x, 0);
    k_colsobel<<<dim3(W / 32, H / TILE_H, IMG_HALF), dim3(32, 8)>>>(0);
    k_hyst<<<dim3(WW64, IMG_HALF), 256>>>(0);
    k_loss<<<LOSS_BLOCKS, 256>>>(y, mask, (float*)d_out, 0);

    // half 1 on s1
    k_rowblur<<<dim3(H / RB_ROWS, IMG_HALF), 256, 0, s1>>>(x, IMG_HALF);
    k_colsobel<<<dim3(W / 32, H / TILE_H, IMG_HALF), dim3(32, 8), 0, s1>>>(IMG_HALF);
    k_hyst<<<dim3(WW64, IMG_HALF), 256, 0, s1>>>(IMG_HALF);
    k_loss<<<LOSS_BLOCKS, 256, 0, s1>>>(y, mask, (float*)d_out, IMG_HALF);

    cudaEventRecord(evJoin, s1);
    cudaStreamWaitEvent(0, evJoin, 0);
}